// round 5
// baseline (speedup 1.0000x reference)
#include <cuda_runtime.h>
#include <cuda_bf16.h>

#define BATCH 4096
#define IN_F 128
#define OUT_F 128
#define NW (IN_F * OUT_F)

// Scratch: 9 repacked generator matrices G_e[o][i] (e=8 holds gen_b weight part),
// plus bias-generator WB[e][o]. Static __device__ arrays (no runtime alloc).
__device__ float d_Gp[9 * 16384];
__device__ float d_WB[9 * 128];

// ---------------------------------------------------------------------------
// Repack: d_Gp[e][o*128+i] = gen_W[(o*128+i)*8 + e]  (e<8),  gen_b[o*128+i] (e=8)
//         d_WB[e][o]       = gen_W[(NW+o)*8 + e]     (e<8),  gen_b[NW+o]    (e=8)
// ---------------------------------------------------------------------------
__global__ void repack_kernel(const float* __restrict__ gen_W,
                              const float* __restrict__ gen_b) {
    int idx = blockIdx.x * blockDim.x + threadIdx.x;
    if (idx < 9 * 16384) {
        int e = idx >> 14;
        int p = idx & 16383;
        d_Gp[idx] = (e < 8) ? gen_W[p * 8 + e] : gen_b[p];
    } else {
        int j = idx - 9 * 16384;
        if (j < 9 * 128) {
            int e = j >> 7;
            int o = j & 127;
            d_WB[j] = (e < 8) ? gen_W[(NW + o) * 8 + e] : gen_b[NW + o];
        }
    }
}

// ---------------------------------------------------------------------------
// Main fused kernel: per block, 32 batch rows x 128 outputs.
//   c[b] = [prelu-MLP(features[b]), 1]  (9 coeffs)
//   out[b,o] = sum_e c[b,e] * (G_e x[b])[o] + sum_e c[b,e]*WB[e][o]
// ---------------------------------------------------------------------------
__global__ __launch_bounds__(256) void hyper_kernel(
    const float* __restrict__ x,
    const float* __restrict__ features,
    const float* __restrict__ fc0_W, const float* __restrict__ fc0_b,
    const float* __restrict__ a0p,
    const float* __restrict__ fc1_W, const float* __restrict__ fc1_b,
    const float* __restrict__ a1p,
    float* __restrict__ out)
{
    __shared__ float4 xsv[32 * 32];     // x tile: 32 rows x 128 cols (as float4)
    __shared__ float  cs[32][9];        // per-sample coefficients
    __shared__ float  wbs[9][128];      // bias generator

    const int tid = threadIdx.x;
    const int b0  = blockIdx.x * 32;

    // Cooperative load of x tile (coalesced float4)
    const float4* xg = (const float4*)(x + (size_t)b0 * IN_F);
    for (int k = tid; k < 32 * 32; k += 256) xsv[k] = xg[k];
    // Bias-generator table
    for (int k = tid; k < 9 * 128; k += 256) ((float*)wbs)[k] = d_WB[k];

    // Tiny MLP: one thread per sample (32 threads)
    if (tid < 32) {
        const int b = b0 + tid;
        const float a0 = a0p[0], a1 = a1p[0];
        float h0[16];
        #pragma unroll
        for (int j = 0; j < 16; j++) {
            float s = fc0_b[j];
            #pragma unroll
            for (int k = 0; k < 10; k++)
                s += features[b * 10 + k] * fc0_W[j * 10 + k];
            h0[j] = (s >= 0.f) ? s : a0 * s;
        }
        #pragma unroll
        for (int e = 0; e < 8; e++) {
            float s = fc1_b[e];
            #pragma unroll
            for (int j = 0; j < 16; j++)
                s += h0[j] * fc1_W[e * 16 + j];
            cs[tid][e] = (s >= 0.f) ? s : a1 * s;
        }
        cs[tid][8] = 1.f;
    }
    __syncthreads();

    const int og = tid & 31;   // warp lane -> output column group (coalesced stores)
    const int bg = tid >> 5;   // warp id  -> batch subgroup

    float acc[4][4];
    #pragma unroll
    for (int bi = 0; bi < 4; bi++)
        #pragma unroll
        for (int oi = 0; oi < 4; oi++) acc[bi][oi] = 0.f;

    for (int e = 0; e < 9; e++) {
        const float4* gb = (const float4*)(d_Gp + e * 16384);
        float cb[4];
        #pragma unroll
        for (int bi = 0; bi < 4; bi++) cb[bi] = cs[bg * 4 + bi][e];

        float z[4][4];
        #pragma unroll
        for (int bi = 0; bi < 4; bi++)
            #pragma unroll
            for (int oi = 0; oi < 4; oi++) z[bi][oi] = 0.f;

        #pragma unroll 2
        for (int i4 = 0; i4 < 32; i4++) {
            float4 g[4], xv[4];
            #pragma unroll
            for (int oi = 0; oi < 4; oi++)
                g[oi] = __ldg(gb + (og + 32 * oi) * 32 + i4);
            #pragma unroll
            for (int bi = 0; bi < 4; bi++)
                xv[bi] = xsv[(bg * 4 + bi) * 32 + i4];
            #pragma unroll
            for (int bi = 0; bi < 4; bi++)
                #pragma unroll
                for (int oi = 0; oi < 4; oi++) {
                    z[bi][oi] += xv[bi].x * g[oi].x;
                    z[bi][oi] += xv[bi].y * g[oi].y;
                    z[bi][oi] += xv[bi].z * g[oi].z;
                    z[bi][oi] += xv[bi].w * g[oi].w;
                }
        }
        #pragma unroll
        for (int bi = 0; bi < 4; bi++)
            #pragma unroll
            for (int oi = 0; oi < 4; oi++)
                acc[bi][oi] += cb[bi] * z[bi][oi];
    }

    // Per-sample bias: sum_e c[b,e] * WB[e][o]
    #pragma unroll
    for (int e = 0; e < 9; e++)
        #pragma unroll
        for (int bi = 0; bi < 4; bi++) {
            float cb = cs[bg * 4 + bi][e];
            #pragma unroll
            for (int oi = 0; oi < 4; oi++)
                acc[bi][oi] += cb * wbs[e][og + 32 * oi];
        }

    // Coalesced stores (lanes span o)
    #pragma unroll
    for (int bi = 0; bi < 4; bi++)
        #pragma unroll
        for (int oi = 0; oi < 4; oi++)
            out[(size_t)(b0 + bg * 4 + bi) * OUT_F + og + 32 * oi] = acc[bi][oi];
}

extern "C" void kernel_launch(void* const* d_in, const int* in_sizes, int n_in,
                              void* d_out, int out_size) {
    const float* x        = (const float*)d_in[0];
    const float* features = (const float*)d_in[1];
    const float* fc0_W    = (const float*)d_in[2];
    const float* fc0_b    = (const float*)d_in[3];
    const float* a0       = (const float*)d_in[4];
    const float* fc1_W    = (const float*)d_in[5];
    const float* fc1_b    = (const float*)d_in[6];
    const float* a1       = (const float*)d_in[7];
    const float* gen_W    = (const float*)d_in[8];
    const float* gen_b    = (const float*)d_in[9];
    float* out = (float*)d_out;

    const int total = 9 * 16384 + 9 * 128;
    repack_kernel<<<(total + 255) / 256, 256>>>(gen_W, gen_b);
    hyper_kernel<<<BATCH / 32, 256>>>(x, features, fc0_W, fc0_b, a0,
                                      fc1_W, fc1_b, a1, out);
}

// round 6
// speedup vs baseline: 2.6748x; 2.6748x over previous
#include <cuda_runtime.h>
#include <cuda_bf16.h>

#define BATCH 4096
#define IN_F 128
#define OUT_F 128
#define NW (IN_F * OUT_F)

// Repacked generator matrices G_e[o][i] (e=8 holds gen_b weight part),
// plus bias-generator WB[e][o]. Static __device__ scratch (no runtime alloc).
__device__ float d_Gp[9 * 16384];
__device__ float d_WB[9 * 128];

// ---------------------------------------------------------------------------
// Repack: d_Gp[e][o*128+i] = gen_W[(o*128+i)*8 + e]  (e<8),  gen_b[o*128+i] (e=8)
//         d_WB[e][o]       = gen_W[(NW+o)*8 + e]     (e<8),  gen_b[NW+o]    (e=8)
// ---------------------------------------------------------------------------
__global__ void repack_kernel(const float* __restrict__ gen_W,
                              const float* __restrict__ gen_b) {
    int idx = blockIdx.x * blockDim.x + threadIdx.x;
    if (idx < 9 * 16384) {
        int e = idx >> 14;
        int p = idx & 16383;
        d_Gp[idx] = (e < 8) ? gen_W[p * 8 + e] : gen_b[p];
    } else {
        int j = idx - 9 * 16384;
        if (j < 9 * 128) {
            int e = j >> 7;
            int o = j & 127;
            d_WB[j] = (e < 8) ? gen_W[(NW + o) * 8 + e] : gen_b[NW + o];
        }
    }
}

// ---------------------------------------------------------------------------
// Main fused kernel: per block, 32 batch rows x 128 outputs.
//   c[b] = [prelu-MLP(features[b]), 1]  (9 coeffs)
//   out[b,o] = sum_e c[b,e] * (G_e x[b])[o] + sum_e c[b,e]*WB[e][o]
//
// G is staged through shared memory:
//   - coalesced global loads (adjacent threads -> adjacent 16B)
//   - double-buffered tiles of 128 o x 16 i (8 KB), register prefetch
//   - smem layout [o][i4] with pitch 5 float4 (80B) -> conflict-free LDS.128
// ---------------------------------------------------------------------------
#define GPITCH 5   // float4 per o-row in smem tile (4 used + 1 pad)

__global__ __launch_bounds__(256) void hyper_kernel(
    const float* __restrict__ x,
    const float* __restrict__ features,
    const float* __restrict__ fc0_W, const float* __restrict__ fc0_b,
    const float* __restrict__ a0p,
    const float* __restrict__ fc1_W, const float* __restrict__ fc1_b,
    const float* __restrict__ a1p,
    float* __restrict__ out)
{
    __shared__ float4 xsv[32 * 32];            // x tile: 32 rows x 128 cols
    __shared__ float  cs[32][9];               // per-sample coefficients
    __shared__ float  wbs[9][128];             // bias generator
    __shared__ float4 gsm[2][128 * GPITCH];    // double-buffered G tile

    const int tid = threadIdx.x;
    const int b0  = blockIdx.x * 32;

    const float4* gp4 = (const float4*)d_Gp;   // e*4096 + o*32 + it*4 + q

    // Per-thread G-tile load coords: each thread loads 2 float4 per tile.
    // idx = tid + 256*k ; o = idx>>2 ; q = idx&3   (128 o x 4 q = 512 float4)
    const int o_a = tid >> 2,          q_a = tid & 3;
    const int o_b = (tid + 256) >> 2,  q_b = (tid + 256) & 3;

    // Prefetch tile 0 (e=0, it=0) immediately — overlaps with x/MLP setup.
    float4 pf0 = gp4[o_a * 32 + q_a];
    float4 pf1 = gp4[o_b * 32 + q_b];

    // Cooperative load of x tile (coalesced float4)
    const float4* xg = (const float4*)(x + (size_t)b0 * IN_F);
    for (int k = tid; k < 32 * 32; k += 256) xsv[k] = xg[k];
    // Bias-generator table
    for (int k = tid; k < 9 * 128; k += 256) ((float*)wbs)[k] = d_WB[k];

    // Tiny MLP: one thread per sample (32 threads)
    if (tid < 32) {
        const int b = b0 + tid;
        const float a0 = a0p[0], a1 = a1p[0];
        float h0[16];
        #pragma unroll
        for (int j = 0; j < 16; j++) {
            float s = fc0_b[j];
            #pragma unroll
            for (int k = 0; k < 10; k++)
                s += features[b * 10 + k] * fc0_W[j * 10 + k];
            h0[j] = (s >= 0.f) ? s : a0 * s;
        }
        #pragma unroll
        for (int e = 0; e < 8; e++) {
            float s = fc1_b[e];
            #pragma unroll
            for (int j = 0; j < 16; j++)
                s += h0[j] * fc1_W[e * 16 + j];
            cs[tid][e] = (s >= 0.f) ? s : a1 * s;
        }
        cs[tid][8] = 1.f;
    }
    __syncthreads();

    // Commit tile 0 into buffer 0
    gsm[0][o_a * GPITCH + q_a] = pf0;
    gsm[0][o_b * GPITCH + q_b] = pf1;
    __syncthreads();

    const int og = tid & 31;   // lane -> output column group (coalesced stores)
    const int bg = tid >> 5;   // warp -> batch subgroup (4 rows)

    float acc[4][4];
    #pragma unroll
    for (int bi = 0; bi < 4; bi++)
        #pragma unroll
        for (int oi = 0; oi < 4; oi++) acc[bi][oi] = 0.f;

    float z[4][4];
    #pragma unroll
    for (int bi = 0; bi < 4; bi++)
        #pragma unroll
        for (int oi = 0; oi < 4; oi++) z[bi][oi] = 0.f;

    // 72 tiles: tile t -> e = t>>3, it = t&7 (16 i-values per tile)
    for (int t = 0; t < 72; t++) {
        const int e  = t >> 3;
        const int it = t & 7;
        const int buf = t & 1;

        // Prefetch next tile into registers (overlaps with compute below)
        if (t < 71) {
            const int tn  = t + 1;
            const int en  = tn >> 3;
            const int itn = tn & 7;
            const int base = en * 4096 + itn * 4;
            pf0 = gp4[base + o_a * 32 + q_a];
            pf1 = gp4[base + o_b * 32 + q_b];
        }

        // Compute this tile from smem
        const float4* gt = gsm[buf];
        #pragma unroll
        for (int i4 = 0; i4 < 4; i4++) {
            float4 g[4], xv[4];
            #pragma unroll
            for (int oi = 0; oi < 4; oi++)
                g[oi] = gt[(og + 32 * oi) * GPITCH + i4];
            #pragma unroll
            for (int bi = 0; bi < 4; bi++)
                xv[bi] = xsv[(bg * 4 + bi) * 32 + it * 4 + i4];  // warp-broadcast
            #pragma unroll
            for (int bi = 0; bi < 4; bi++)
                #pragma unroll
                for (int oi = 0; oi < 4; oi++) {
                    z[bi][oi] += xv[bi].x * g[oi].x;
                    z[bi][oi] += xv[bi].y * g[oi].y;
                    z[bi][oi] += xv[bi].z * g[oi].z;
                    z[bi][oi] += xv[bi].w * g[oi].w;
                }
        }

        // End of this e: fold z into acc with per-sample coefficient
        if (it == 7) {
            #pragma unroll
            for (int bi = 0; bi < 4; bi++) {
                const float cb = cs[bg * 4 + bi][e];
                #pragma unroll
                for (int oi = 0; oi < 4; oi++) {
                    acc[bi][oi] += cb * z[bi][oi];
                    z[bi][oi] = 0.f;
                }
            }
        }

        // Commit prefetched tile into the other buffer
        if (t < 71) {
            gsm[buf ^ 1][o_a * GPITCH + q_a] = pf0;
            gsm[buf ^ 1][o_b * GPITCH + q_b] = pf1;
            __syncthreads();
        }
    }

    // Per-sample bias: sum_e c[b,e] * WB[e][o]
    #pragma unroll
    for (int e = 0; e < 9; e++)
        #pragma unroll
        for (int bi = 0; bi < 4; bi++) {
            const float cb = cs[bg * 4 + bi][e];
            #pragma unroll
            for (int oi = 0; oi < 4; oi++)
                acc[bi][oi] += cb * wbs[e][og + 32 * oi];
        }

    // Coalesced stores (lanes span o)
    #pragma unroll
    for (int bi = 0; bi < 4; bi++)
        #pragma unroll
        for (int oi = 0; oi < 4; oi++)
            out[(size_t)(b0 + bg * 4 + bi) * OUT_F + og + 32 * oi] = acc[bi][oi];
}

extern "C" void kernel_launch(void* const* d_in, const int* in_sizes, int n_in,
                              void* d_out, int out_size) {
    const float* x        = (const float*)d_in[0];
    const float* features = (const float*)d_in[1];
    const float* fc0_W    = (const float*)d_in[2];
    const float* fc0_b    = (const float*)d_in[3];
    const float* a0       = (const float*)d_in[4];
    const float* fc1_W    = (const float*)d_in[5];
    const float* fc1_b    = (const float*)d_in[6];
    const float* a1       = (const float*)d_in[7];
    const float* gen_W    = (const float*)d_in[8];
    const float* gen_b    = (const float*)d_in[9];
    float* out = (float*)d_out;

    const int total = 9 * 16384 + 9 * 128;
    repack_kernel<<<(total + 255) / 256, 256>>>(gen_W, gen_b);
    hyper_kernel<<<BATCH / 32, 256>>>(x, features, fc0_W, fc0_b, a0,
                                      fc1_W, fc1_b, a1, out);
}

// round 8
// speedup vs baseline: 4.9647x; 1.8561x over previous
#include <cuda_runtime.h>
#include <cuda_bf16.h>
#include <cstdint>

#define BATCH 4096
#define IN_F 128
#define OUT_F 128
#define NW (IN_F * OUT_F)
#define KP 1216              // padded K: 1152 (9e*128i) + 9 bias cols + 55 pad -> 38 chunks of 32
#define NCHUNK 38

// Static scratch (no runtime alloc): U operand, repacked B operand.
__device__ float d_U[(size_t)BATCH * KP];
__device__ float d_Bt[OUT_F * KP];

// ---------------------------------------------------------------------------
// Helpers (baseline PTX only — no sm_103a-suffixed features)
// ---------------------------------------------------------------------------
__device__ __forceinline__ uint32_t smem_u32(const void* p) {
    uint32_t a;
    asm("{ .reg .u64 t; cvta.to.shared.u64 t, %1; cvt.u32.u64 %0, t; }" : "=r"(a) : "l"(p));
    return a;
}
__device__ __forceinline__ float tf32r(float x) {
    uint32_t r;
    asm("cvt.rn.tf32.f32 %0, %1;" : "=r"(r) : "f"(x));
    return __uint_as_float(r);
}
__device__ __forceinline__ void cp16(uint32_t s, const void* g) {
    asm volatile("cp.async.cg.shared.global [%0], [%1], 16;" :: "r"(s), "l"(g));
}
#define CP_COMMIT() asm volatile("cp.async.commit_group;" ::: "memory")
#define CP_WAIT1()  asm volatile("cp.async.wait_group 1;" ::: "memory")
#define CP_WAIT0()  asm volatile("cp.async.wait_group 0;" ::: "memory")

__device__ __forceinline__ void mma_tf32(float& d0, float& d1, float& d2, float& d3,
                                         uint32_t a0, uint32_t a1, uint32_t a2, uint32_t a3,
                                         uint32_t b0, uint32_t b1) {
    asm volatile(
        "mma.sync.aligned.m16n8k8.row.col.f32.tf32.tf32.f32 "
        "{%0,%1,%2,%3}, {%4,%5,%6,%7}, {%8,%9}, {%0,%1,%2,%3};"
        : "+f"(d0), "+f"(d1), "+f"(d2), "+f"(d3)
        : "r"(a0), "r"(a1), "r"(a2), "r"(a3), "r"(b0), "r"(b1));
}

// ---------------------------------------------------------------------------
// Prep 1: build U[b][k] (tf32-rounded), fusing the tiny MLP per batch row.
//   k<1152:  c[b][k>>7] * x[b][k&127]
//   1152..1160: c[b][k-1152]   (bias columns; pairs with WB rows in Bt)
//   else 0 (padding)
// ---------------------------------------------------------------------------
__global__ __launch_bounds__(256) void u_kernel(
    const float* __restrict__ x, const float* __restrict__ features,
    const float* __restrict__ fc0_W, const float* __restrict__ fc0_b,
    const float* __restrict__ a0p,
    const float* __restrict__ fc1_W, const float* __restrict__ fc1_b,
    const float* __restrict__ a1p)
{
    __shared__ float h0s[16];
    __shared__ float cs[9];
    const int b = blockIdx.x;
    const int tid = threadIdx.x;

    // Layer 0: 16 threads, one hidden unit each
    if (tid < 16) {
        const float a0 = a0p[0];
        float s = fc0_b[tid];
        #pragma unroll
        for (int k = 0; k < 10; k++)
            s += features[b * 10 + k] * fc0_W[tid * 10 + k];
        h0s[tid] = (s >= 0.f) ? s : a0 * s;
    }
    __syncthreads();
    // Layer 1: 8 threads, one output each
    if (tid < 8) {
        const float a1 = a1p[0];
        float s = fc1_b[tid];
        #pragma unroll
        for (int j = 0; j < 16; j++)
            s += h0s[j] * fc1_W[tid * 16 + j];
        cs[tid] = (s >= 0.f) ? s : a1 * s;
    }
    if (tid == 8) cs[8] = 1.f;
    __syncthreads();

    float* Ur = d_U + (size_t)b * KP;
    const float* xr = x + (size_t)b * IN_F;
    #pragma unroll 1
    for (int k = tid; k < KP; k += 256) {
        float u;
        if (k < 1152)       u = cs[k >> 7] * xr[k & 127];
        else if (k < 1161)  u = cs[k - 1152];
        else                u = 0.f;
        Ur[k] = tf32r(u);
    }
}

// ---------------------------------------------------------------------------
// Prep 2: Bt[o][k] (tf32-rounded):
//   k<1152: e=k>>7, i=k&127, p=o*128+i -> gen_W[p*8+e] (e<8) / gen_b[p] (e==8)
//   1152..1160: e=k-1152 -> gen_W[(NW+o)*8+e] (e<8) / gen_b[NW+o] (e==8)
// ---------------------------------------------------------------------------
__global__ __launch_bounds__(256) void b_kernel(const float* __restrict__ gen_W,
                                                const float* __restrict__ gen_b) {
    const int o = blockIdx.x;
    for (int k = threadIdx.x; k < KP; k += 256) {
        float v;
        if (k < 1152) {
            const int e = k >> 7, i = k & 127, p = o * 128 + i;
            v = (e < 8) ? gen_W[p * 8 + e] : gen_b[p];
        } else if (k < 1161) {
            const int e = k - 1152;
            v = (e < 8) ? gen_W[(NW + o) * 8 + e] : gen_b[NW + o];
        } else v = 0.f;
        d_Bt[o * KP + k] = tf32r(v);
    }
}

// ---------------------------------------------------------------------------
// GEMM: out[4096,128] = U @ Bt^T via mma.sync m16n8k8 tf32.
// CTA: 256 threads (8 warps), tile M=32 x N=128, K chunks of 32,
// cp.async double-buffered smem. Warp grid 2(M) x 4(N), warp tile 16x32.
// smem pitch 36 floats -> fragment LDS conflict-free (4g+q distinct mod 32).
// ---------------------------------------------------------------------------
#define AP 36

__global__ __launch_bounds__(256, 1) void gemm_kernel(float* __restrict__ out) {
    __shared__ float As[2][32 * AP];    // 2 x 4.6 KB
    __shared__ float Bs[2][128 * AP];   // 2 x 18.4 KB  (total 46 KB)

    const int tid = threadIdx.x, wid = tid >> 5, lid = tid & 31;
    const int b0 = blockIdx.x * 32;
    const int wr = wid & 1;        // warp row in M (0..1), 16 rows each
    const int wc = wid >> 1;       // warp col in N (0..3), 32 cols each
    const int m0 = wr * 16, n0 = wc * 32;
    const int g = lid >> 2, q = lid & 3;

    const uint32_t sa[2] = { smem_u32(As[0]), smem_u32(As[1]) };
    const uint32_t sb[2] = { smem_u32(Bs[0]), smem_u32(Bs[1]) };

    const float4* Ug = (const float4*)(d_U + (size_t)b0 * KP);   // row pitch 304 f4
    const float4* Bg = (const float4*)d_Bt;

    // Stage chunk c into buffer buf. A: 256 f4 (1/thread). B: 1024 f4 (4/thread).
    auto stage = [&](int c, int buf) {
        const int kq = c * 8;
        {
            const int r = tid >> 3, p = tid & 7;
            cp16(sa[buf] + (r * AP + p * 4) * 4, Ug + r * 304 + kq + p);
        }
        #pragma unroll
        for (int j = 0; j < 4; j++) {
            const int idx = tid + 256 * j;
            const int r = idx >> 3, p = idx & 7;
            cp16(sb[buf] + (r * AP + p * 4) * 4, Bg + r * 304 + kq + p);
        }
        CP_COMMIT();
    };

    float acc[4][4];
    #pragma unroll
    for (int ni = 0; ni < 4; ni++)
        #pragma unroll
        for (int r = 0; r < 4; r++) acc[ni][r] = 0.f;

    stage(0, 0);
    stage(1, 1);

    for (int c = 0; c < NCHUNK; c++) {
        if (c == NCHUNK - 1) { CP_WAIT0(); } else { CP_WAIT1(); }
        __syncthreads();

        const int buf = c & 1;
        const float* Ab = As[buf];
        const float* Bb = Bs[buf];

        #pragma unroll
        for (int ki = 0; ki < 4; ki++) {
            const int k0 = ki * 8;
            uint32_t a0 = __float_as_uint(Ab[(m0 + g)     * AP + k0 + q]);
            uint32_t a1 = __float_as_uint(Ab[(m0 + g + 8) * AP + k0 + q]);
            uint32_t a2 = __float_as_uint(Ab[(m0 + g)     * AP + k0 + q + 4]);
            uint32_t a3 = __float_as_uint(Ab[(m0 + g + 8) * AP + k0 + q + 4]);
            #pragma unroll
            for (int ni = 0; ni < 4; ni++) {
                uint32_t bb0 = __float_as_uint(Bb[(n0 + ni * 8 + g) * AP + k0 + q]);
                uint32_t bb1 = __float_as_uint(Bb[(n0 + ni * 8 + g) * AP + k0 + q + 4]);
                mma_tf32(acc[ni][0], acc[ni][1], acc[ni][2], acc[ni][3],
                         a0, a1, a2, a3, bb0, bb1);
            }
        }

        __syncthreads();                       // done reading buf before restage
        if (c + 2 < NCHUNK) stage(c + 2, buf);
    }

    // Epilogue: c0/c1 -> (row m0+g, cols n0+2q, +1); c2/c3 -> row +8.
    #pragma unroll
    for (int ni = 0; ni < 4; ni++) {
        const int col = n0 + ni * 8 + 2 * q;
        float2 lo = make_float2(acc[ni][0], acc[ni][1]);
        float2 hi = make_float2(acc[ni][2], acc[ni][3]);
        *(float2*)(out + (size_t)(b0 + m0 + g)     * OUT_F + col) = lo;
        *(float2*)(out + (size_t)(b0 + m0 + g + 8) * OUT_F + col) = hi;
    }
}

// ---------------------------------------------------------------------------
extern "C" void kernel_launch(void* const* d_in, const int* in_sizes, int n_in,
                              void* d_out, int out_size) {
    const float* x        = (const float*)d_in[0];
    const float* features = (const float*)d_in[1];
    const float* fc0_W    = (const float*)d_in[2];
    const float* fc0_b    = (const float*)d_in[3];
    const float* a0       = (const float*)d_in[4];
    const float* fc1_W    = (const float*)d_in[5];
    const float* fc1_b    = (const float*)d_in[6];
    const float* a1       = (const float*)d_in[7];
    const float* gen_W    = (const float*)d_in[8];
    const float* gen_b    = (const float*)d_in[9];
    float* out = (float*)d_out;

    u_kernel<<<BATCH, 256>>>(x, features, fc0_W, fc0_b, a0, fc1_W, fc1_b, a1);
    b_kernel<<<OUT_F, 256>>>(gen_W, gen_b);
    gemm_kernel<<<BATCH / 32, 256>>>(out);
}

// round 9
// speedup vs baseline: 6.3054x; 1.2700x over previous
#include <cuda_runtime.h>
#include <cuda_bf16.h>
#include <cstdint>

#define BATCH 4096
#define IN_F 128
#define OUT_F 128
#define NW (IN_F * OUT_F)
#define KP 1216              // padded K: 1152 (9e*128i) + 9 bias cols + pad
#define NCHUNK 37            // 36 x-chunks + 1 bias chunk

// Static scratch (no runtime alloc): repacked B operand only (U is fused away).
__device__ float d_Bt[OUT_F * KP];

// ---------------------------------------------------------------------------
// Helpers (baseline PTX only — no sm_103a-suffixed features; ptxas on this
// toolchain compiles through compute_103 and rejects tcgen05)
// ---------------------------------------------------------------------------
__device__ __forceinline__ uint32_t smem_u32(const void* p) {
    uint32_t a;
    asm("{ .reg .u64 t; cvta.to.shared.u64 t, %1; cvt.u32.u64 %0, t; }" : "=r"(a) : "l"(p));
    return a;
}
__device__ __forceinline__ float tf32r(float x) {
    uint32_t r;
    asm("cvt.rn.tf32.f32 %0, %1;" : "=r"(r) : "f"(x));
    return __uint_as_float(r);
}
__device__ __forceinline__ uint32_t tf32u(float x) {
    uint32_t r;
    asm("cvt.rn.tf32.f32 %0, %1;" : "=r"(r) : "f"(x));
    return r;
}
__device__ __forceinline__ void cp16(uint32_t s, const void* g) {
    asm volatile("cp.async.cg.shared.global [%0], [%1], 16;" :: "r"(s), "l"(g));
}
#define CP_COMMIT() asm volatile("cp.async.commit_group;" ::: "memory")
#define CP_WAIT1()  asm volatile("cp.async.wait_group 1;" ::: "memory")
#define CP_WAIT0()  asm volatile("cp.async.wait_group 0;" ::: "memory")

__device__ __forceinline__ void mma_tf32(float& d0, float& d1, float& d2, float& d3,
                                         uint32_t a0, uint32_t a1, uint32_t a2, uint32_t a3,
                                         uint32_t b0, uint32_t b1) {
    asm volatile(
        "mma.sync.aligned.m16n8k8.row.col.f32.tf32.tf32.f32 "
        "{%0,%1,%2,%3}, {%4,%5,%6,%7}, {%8,%9}, {%0,%1,%2,%3};"
        : "+f"(d0), "+f"(d1), "+f"(d2), "+f"(d3)
        : "r"(a0), "r"(a1), "r"(a2), "r"(a3), "r"(b0), "r"(b1));
}

// ---------------------------------------------------------------------------
// Prep: Bt[o][k] (tf32-rounded):
//   k<1152: e=k>>7, i=k&127, p=o*128+i -> gen_W[p*8+e] (e<8) / gen_b[p] (e==8)
//   1152..1160: e=k-1152 -> gen_W[(NW+o)*8+e] (e<8) / gen_b[NW+o] (e==8)
//   else 0
// ---------------------------------------------------------------------------
__global__ __launch_bounds__(256) void b_kernel(const float* __restrict__ gen_W,
                                                const float* __restrict__ gen_b) {
    const int o = blockIdx.x;
    for (int k = threadIdx.x; k < KP; k += 256) {
        float v;
        if (k < 1152) {
            const int e = k >> 7, i = k & 127, p = o * 128 + i;
            v = (e < 8) ? gen_W[p * 8 + e] : gen_b[p];
        } else if (k < 1161) {
            const int e = k - 1152;
            v = (e < 8) ? gen_W[(NW + o) * 8 + e] : gen_b[NW + o];
        } else v = 0.f;
        d_Bt[o * KP + k] = tf32r(v);
    }
}

// ---------------------------------------------------------------------------
// Fused GEMM: out[4096,128] = U @ Bt^T, where U[b,k] = c[b,e]*x[b,i] is built
// in-register from an smem x-tile (no U materialization).
// CTA: 256 threads, tile M=32 x N=128. K chunks of 32; within a chunk, e=c>>2
// is constant, so A-frag = tf32(cb_row * x_frag). Chunk 36 = bias columns
// (x-tile extension cols 128.. hold c[b,e], scale 1).
// B double-buffered via cp.async (pitch 36: frag offsets 4g+q distinct mod 32).
// x-tile pitch 164: same conflict-free property.
// ---------------------------------------------------------------------------
#define BP 36     // B smem pitch (floats)
#define XP 164    // x smem pitch (floats), 41 float4

__global__ __launch_bounds__(256, 1) void gemm_kernel(
    const float* __restrict__ x,
    const float* __restrict__ features,
    const float* __restrict__ fc0_W, const float* __restrict__ fc0_b,
    const float* __restrict__ a0p,
    const float* __restrict__ fc1_W, const float* __restrict__ fc1_b,
    const float* __restrict__ a1p,
    float* __restrict__ out)
{
    __shared__ __align__(16) float xs[32 * XP];      // 21.0 KB: cols 0-127 x, 128-136 c, rest 0
    __shared__ __align__(16) float Bs[2][128 * BP];  // 2 x 18.4 KB

    const int tid = threadIdx.x, wid = tid >> 5, lid = tid & 31;
    const int b0 = blockIdx.x * 32;
    const int wr = wid & 1;        // warp row in M (16 rows each)
    const int wc = wid >> 1;       // warp col in N (32 cols each)
    const int m0 = wr * 16, n0 = wc * 32;
    const int g = lid >> 2, q = lid & 3;

    const uint32_t sb[2] = { smem_u32(Bs[0]), smem_u32(Bs[1]) };
    const float4* Bg = (const float4*)d_Bt;          // row pitch 304 f4

    // B staging: 1024 f4 per chunk, 4 per thread, coalesced, SW-free pitch 36.
    auto stageB = [&](int c, int buf) {
        const int kq = c * 8;
        #pragma unroll
        for (int j = 0; j < 4; j++) {
            const int idx = tid + 256 * j;
            const int r = idx >> 3, p = idx & 7;
            cp16(sb[buf] + (r * BP + p * 4) * 4, Bg + r * 304 + kq + p);
        }
        CP_COMMIT();
    };

    stageB(0, 0);
    stageB(1, 1);

    // x tile: 32 rows x 128 cols as float4 into pitched smem
    {
        const float4* xg = (const float4*)(x + (size_t)b0 * IN_F);
        float4* xs4 = (float4*)xs;
        #pragma unroll
        for (int j = 0; j < 4; j++) {
            const int idx = tid + 256 * j;          // 0..1023
            const int r = idx >> 5, c4 = idx & 31;
            xs4[r * 41 + c4] = xg[idx];
        }
    }

    // Tiny MLP: threads 0-31, one sample each; write coeffs into x-tile
    // extension (cols 128-136), zero cols 137-163.
    if (tid < 32) {
        const int b = b0 + tid;
        const float a0 = a0p[0], a1 = a1p[0];
        float h0[16];
        #pragma unroll
        for (int j = 0; j < 16; j++) {
            float s = fc0_b[j];
            #pragma unroll
            for (int k = 0; k < 10; k++)
                s += features[b * 10 + k] * fc0_W[j * 10 + k];
            h0[j] = (s >= 0.f) ? s : a0 * s;
        }
        float* xr = xs + tid * XP + 128;
        #pragma unroll
        for (int e = 0; e < 8; e++) {
            float s = fc1_b[e];
            #pragma unroll
            for (int j = 0; j < 16; j++)
                s += h0[j] * fc1_W[e * 16 + j];
            xr[e] = (s >= 0.f) ? s : a1 * s;
        }
        xr[8] = 1.f;
        #pragma unroll
        for (int j = 9; j < 36; j++) xr[j] = 0.f;
    }

    float acc[4][4];
    #pragma unroll
    for (int ni = 0; ni < 4; ni++)
        #pragma unroll
        for (int r = 0; r < 4; r++) acc[ni][r] = 0.f;

    const float* x0 = xs + (m0 + g) * XP;        // this lane's row pair
    const float* x1 = xs + (m0 + g + 8) * XP;

    for (int c = 0; c < NCHUNK; c++) {
        if (c == NCHUNK - 1) { CP_WAIT0(); } else { CP_WAIT1(); }
        __syncthreads();     // first iter: also publishes xs (x tile + coeffs)

        const int buf = c & 1;
        const float* Bb = Bs[buf];

        // chunk geometry: e constant within chunk
        float cb0, cb1;
        int i0;
        if (c < 36) {
            const int e = c >> 2;
            i0 = (c & 3) * 32;
            cb0 = x0[128 + e];
            cb1 = x1[128 + e];
        } else {            // bias chunk: A = coeff columns directly
            i0 = 128;
            cb0 = 1.f;
            cb1 = 1.f;
        }

        #pragma unroll
        for (int ki = 0; ki < 4; ki++) {
            const int col = i0 + ki * 8 + q;
            uint32_t a0 = tf32u(cb0 * x0[col]);
            uint32_t a1 = tf32u(cb1 * x1[col]);
            uint32_t a2 = tf32u(cb0 * x0[col + 4]);
            uint32_t a3 = tf32u(cb1 * x1[col + 4]);
            const int k0 = ki * 8;
            #pragma unroll
            for (int ni = 0; ni < 4; ni++) {
                uint32_t bb0 = __float_as_uint(Bb[(n0 + ni * 8 + g) * BP + k0 + q]);
                uint32_t bb1 = __float_as_uint(Bb[(n0 + ni * 8 + g) * BP + k0 + q + 4]);
                mma_tf32(acc[ni][0], acc[ni][1], acc[ni][2], acc[ni][3],
                         a0, a1, a2, a3, bb0, bb1);
            }
        }

        __syncthreads();                       // done reading buf before restage
        if (c + 2 < NCHUNK) stageB(c + 2, buf);
    }

    // Epilogue: c0/c1 -> (row m0+g, cols n0+8ni+2q); c2/c3 -> row +8.
    #pragma unroll
    for (int ni = 0; ni < 4; ni++) {
        const int col = n0 + ni * 8 + 2 * q;
        float2 lo = make_float2(acc[ni][0], acc[ni][1]);
        float2 hi = make_float2(acc[ni][2], acc[ni][3]);
        *(float2*)(out + (size_t)(b0 + m0 + g)     * OUT_F + col) = lo;
        *(float2*)(out + (size_t)(b0 + m0 + g + 8) * OUT_F + col) = hi;
    }
}

// ---------------------------------------------------------------------------
extern "C" void kernel_launch(void* const* d_in, const int* in_sizes, int n_in,
                              void* d_out, int out_size) {
    const float* x        = (const float*)d_in[0];
    const float* features = (const float*)d_in[1];
    const float* fc0_W    = (const float*)d_in[2];
    const float* fc0_b    = (const float*)d_in[3];
    const float* a0       = (const float*)d_in[4];
    const float* fc1_W    = (const float*)d_in[5];
    const float* fc1_b    = (const float*)d_in[6];
    const float* a1       = (const float*)d_in[7];
    const float* gen_W    = (const float*)d_in[8];
    const float* gen_b    = (const float*)d_in[9];
    float* out = (float*)d_out;

    b_kernel<<<OUT_F, 256>>>(gen_W, gen_b);
    gemm_kernel<<<BATCH / 32, 256>>>(x, features, fc0_W, fc0_b, a0,
                                     fc1_W, fc1_b, a1, out);
}

// round 10
// speedup vs baseline: 6.6921x; 1.0613x over previous
#include <cuda_runtime.h>
#include <cuda_bf16.h>
#include <cstdint>

#define BATCH 4096
#define IN_F 128
#define OUT_F 128
#define NW (IN_F * OUT_F)
#define KP 1216              // padded K: 1152 (9e*128i) + 9 bias cols + pad
#define NCHUNK 37            // 36 x-chunks + 1 bias chunk

// Static scratch (no runtime alloc): repacked B operand only.
__device__ float d_Bt[OUT_F * KP];

// ---------------------------------------------------------------------------
// Helpers (baseline PTX only — this toolchain compiles via compute_103 and
// rejects tcgen05/sm_103a-suffixed features)
// ---------------------------------------------------------------------------
__device__ __forceinline__ uint32_t smem_u32(const void* p) {
    uint32_t a;
    asm("{ .reg .u64 t; cvta.to.shared.u64 t, %1; cvt.u32.u64 %0, t; }" : "=r"(a) : "l"(p));
    return a;
}
__device__ __forceinline__ float tf32r(float x) {
    uint32_t r;
    asm("cvt.rn.tf32.f32 %0, %1;" : "=r"(r) : "f"(x));
    return __uint_as_float(r);
}
__device__ __forceinline__ uint32_t tf32u(float x) {
    uint32_t r;
    asm("cvt.rn.tf32.f32 %0, %1;" : "=r"(r) : "f"(x));
    return r;
}
__device__ __forceinline__ void cp16(uint32_t s, const void* g) {
    asm volatile("cp.async.cg.shared.global [%0], [%1], 16;" :: "r"(s), "l"(g));
}
#define CP_COMMIT() asm volatile("cp.async.commit_group;" ::: "memory")
#define CP_WAIT2()  asm volatile("cp.async.wait_group 2;" ::: "memory")
#define NBAR(id)    asm volatile("bar.sync %0, 256;" :: "r"(id) : "memory")

__device__ __forceinline__ void mma_tf32(float& d0, float& d1, float& d2, float& d3,
                                         uint32_t a0, uint32_t a1, uint32_t a2, uint32_t a3,
                                         uint32_t b0, uint32_t b1) {
    asm volatile(
        "mma.sync.aligned.m16n8k8.row.col.f32.tf32.tf32.f32 "
        "{%0,%1,%2,%3}, {%4,%5,%6,%7}, {%8,%9}, {%0,%1,%2,%3};"
        : "+f"(d0), "+f"(d1), "+f"(d2), "+f"(d3)
        : "r"(a0), "r"(a1), "r"(a2), "r"(a3), "r"(b0), "r"(b1));
}

// ---------------------------------------------------------------------------
// Prep: Bt[o][k] (tf32-rounded)
// ---------------------------------------------------------------------------
__global__ __launch_bounds__(256) void b_kernel(const float* __restrict__ gen_W,
                                                const float* __restrict__ gen_b) {
    const int o = blockIdx.x;
    for (int k = threadIdx.x; k < KP; k += 256) {
        float v;
        if (k < 1152) {
            const int e = k >> 7, i = k & 127, p = o * 128 + i;
            v = (e < 8) ? gen_W[p * 8 + e] : gen_b[p];
        } else if (k < 1161) {
            const int e = k - 1152;
            v = (e < 8) ? gen_W[(NW + o) * 8 + e] : gen_b[NW + o];
        } else v = 0.f;
        d_Bt[o * KP + k] = tf32r(v);
    }
}

// ---------------------------------------------------------------------------
// Fused GEMM, K-split x2 across warp groups:
//   CTA = 512 threads (2 groups of 8 warps). Tile M=32 x N=128.
//   Group h handles chunks c = 2j+h with its own 4-deep cp.async ring and
//   named barrier (one bar per chunk). Partials reduced via smem at the end.
//   A-frags built in-register: U[b,k] = c[b,e]*x[b,i] from smem x-tile.
// ---------------------------------------------------------------------------
#define BP 36            // B smem pitch (floats)
#define XP 164           // x smem pitch (floats), 41 float4
#define NBUF 4
#define XS_FLOATS (32 * XP)                 // 5248
#define BBUF_FLOATS (128 * BP)              // 4608
#define SMEM_BYTES ((XS_FLOATS + 2 * NBUF * BBUF_FLOATS) * 4)   // 168448

__global__ __launch_bounds__(512, 1) void gemm_kernel(
    const float* __restrict__ x,
    const float* __restrict__ features,
    const float* __restrict__ fc0_W, const float* __restrict__ fc0_b,
    const float* __restrict__ a0p,
    const float* __restrict__ fc1_W, const float* __restrict__ fc1_b,
    const float* __restrict__ a1p,
    float* __restrict__ out)
{
    extern __shared__ __align__(16) float sm[];
    float* xs = sm;                                   // x tile + coeff extension

    const int tid = threadIdx.x, wid = tid >> 5, lid = tid & 31;
    const int h   = wid >> 3;          // warp group (0: even chunks, 1: odd)
    const int w8  = wid & 7;
    const int tg  = tid & 255;         // thread id within group
    const int b0  = blockIdx.x * 32;
    const int wr = w8 & 1, wc = w8 >> 1;
    const int m0 = wr * 16, n0 = wc * 32;
    const int g = lid >> 2, q = lid & 3;
    const int nch = h ? 18 : 19;       // chunks for this group

    const uint32_t su = smem_u32(sm);
    const uint32_t gb_base = su + (XS_FLOATS + h * NBUF * BBUF_FLOATS) * 4;
    const float4* Bg = (const float4*)d_Bt;           // row pitch 304 f4

    // Stage group chunk jj (global chunk 2*jj+h) into ring buffer jj%4.
    // 1024 f4 per chunk, 4 per thread (256 threads of this group), coalesced.
    auto stage = [&](int jj) {
        const int c = 2 * jj + h;
        const uint32_t dst = gb_base + (jj & 3) * (BBUF_FLOATS * 4);
        const float4* src = Bg + c * 8;
        #pragma unroll
        for (int k2 = 0; k2 < 4; k2++) {
            const int idx = tg + 256 * k2;
            const int r = idx >> 3, p = idx & 7;
            cp16(dst + (r * BP + p * 4) * 4, src + r * 304 + p);
        }
        CP_COMMIT();
    };

    stage(0);
    stage(1);

    // x tile: 32 rows x 128 cols (float4) into pitched smem, 512 threads.
    {
        const float4* xg = (const float4*)(x + (size_t)b0 * IN_F);
        float4* xs4 = (float4*)xs;
        #pragma unroll
        for (int j = 0; j < 2; j++) {
            const int idx = tid + 512 * j;            // 0..1023
            const int r = idx >> 5, c4 = idx & 31;
            xs4[r * 41 + c4] = xg[idx];
        }
    }

    // Tiny MLP: threads 0-31, one sample each; coeffs -> x-tile cols 128-136.
    if (tid < 32) {
        const int b = b0 + tid;
        const float a0 = a0p[0], a1 = a1p[0];
        float h0[16];
        #pragma unroll
        for (int j = 0; j < 16; j++) {
            float s = fc0_b[j];
            #pragma unroll
            for (int k = 0; k < 10; k++)
                s += features[b * 10 + k] * fc0_W[j * 10 + k];
            h0[j] = (s >= 0.f) ? s : a0 * s;
        }
        float* xr = xs + tid * XP + 128;
        #pragma unroll
        for (int e = 0; e < 8; e++) {
            float s = fc1_b[e];
            #pragma unroll
            for (int j = 0; j < 16; j++)
                s += h0[j] * fc1_W[e * 16 + j];
            xr[e] = (s >= 0.f) ? s : a1 * s;
        }
        xr[8] = 1.f;
        #pragma unroll
        for (int j = 9; j < 36; j++) xr[j] = 0.f;
    }
    __syncthreads();

    float acc[4][4];
    #pragma unroll
    for (int ni = 0; ni < 4; ni++)
        #pragma unroll
        for (int r = 0; r < 4; r++) acc[ni][r] = 0.f;

    const float* x0 = xs + (m0 + g) * XP;
    const float* x1 = xs + (m0 + g + 8) * XP;

    // Mainloop: stage(jj+2) -> wait(2) -> named bar -> compute(jj).
    // Buffer (jj+2)%4 was last computed at jj-2, finished by all warps before
    // the previous barrier -> write-safe. Every thread's wait precedes the
    // barrier -> chunk jj data visible to all readers.
    for (int jj = 0; jj < nch; jj++) {
        if (jj + 2 < nch) stage(jj + 2); else CP_COMMIT();
        CP_WAIT2();
        NBAR(h + 1);

        const float* Bb = sm + XS_FLOATS + (h * NBUF + (jj & 3)) * BBUF_FLOATS;
        const int c = 2 * jj + h;

        float cb0, cb1;
        int i0;
        if (c < 36) {
            const int e = c >> 2;
            i0 = (c & 3) * 32;
            cb0 = x0[128 + e];
            cb1 = x1[128 + e];
        } else {            // bias chunk
            i0 = 128;
            cb0 = 1.f;
            cb1 = 1.f;
        }

        #pragma unroll
        for (int ki = 0; ki < 4; ki++) {
            const int col = i0 + ki * 8 + q;
            uint32_t a0 = tf32u(cb0 * x0[col]);
            uint32_t a1 = tf32u(cb1 * x1[col]);
            uint32_t a2 = tf32u(cb0 * x0[col + 4]);
            uint32_t a3 = tf32u(cb1 * x1[col + 4]);
            const int k0 = ki * 8;
            #pragma unroll
            for (int ni = 0; ni < 4; ni++) {
                uint32_t bb0 = __float_as_uint(Bb[(n0 + ni * 8 + g) * BP + k0 + q]);
                uint32_t bb1 = __float_as_uint(Bb[(n0 + ni * 8 + g) * BP + k0 + q + 4]);
                mma_tf32(acc[ni][0], acc[ni][1], acc[ni][2], acc[ni][3],
                         a0, a1, a2, a3, bb0, bb1);
            }
        }
    }

    // Reduce group 1 partials into group 0, then store.
    // red lives in group 1's ring buffer 0 (only group 1 touched it).
    float* red = sm + XS_FLOATS + (1 * NBUF + 0) * BBUF_FLOATS;   // 4096 of 4608 used
    if (h == 1) {
        #pragma unroll
        for (int ni = 0; ni < 4; ni++) {
            const int col = n0 + ni * 8 + 2 * q;
            red[(m0 + g) * 128 + col]     = acc[ni][0];
            red[(m0 + g) * 128 + col + 1] = acc[ni][1];
            red[(m0 + g + 8) * 128 + col]     = acc[ni][2];
            red[(m0 + g + 8) * 128 + col + 1] = acc[ni][3];
        }
    }
    __syncthreads();
    if (h == 0) {
        #pragma unroll
        for (int ni = 0; ni < 4; ni++) {
            const int col = n0 + ni * 8 + 2 * q;
            float2 lo = make_float2(acc[ni][0] + red[(m0 + g) * 128 + col],
                                    acc[ni][1] + red[(m0 + g) * 128 + col + 1]);
            float2 hi = make_float2(acc[ni][2] + red[(m0 + g + 8) * 128 + col],
                                    acc[ni][3] + red[(m0 + g + 8) * 128 + col + 1]);
            *(float2*)(out + (size_t)(b0 + m0 + g)     * OUT_F + col) = lo;
            *(float2*)(out + (size_t)(b0 + m0 + g + 8) * OUT_F + col) = hi;
        }
    }
}

// ---------------------------------------------------------------------------
extern "C" void kernel_launch(void* const* d_in, const int* in_sizes, int n_in,
                              void* d_out, int out_size) {
    const float* x        = (const float*)d_in[0];
    const float* features = (const float*)d_in[1];
    const float* fc0_W    = (const float*)d_in[2];
    const float* fc0_b    = (const float*)d_in[3];
    const float* a0       = (const float*)d_in[4];
    const float* fc1_W    = (const float*)d_in[5];
    const float* fc1_b    = (const float*)d_in[6];
    const float* a1       = (const float*)d_in[7];
    const float* gen_W    = (const float*)d_in[8];
    const float* gen_b    = (const float*)d_in[9];
    float* out = (float*)d_out;

    b_kernel<<<OUT_F, 256>>>(gen_W, gen_b);

    static int cfg_done = 0;
    if (!cfg_done) {
        cudaFuncSetAttribute(gemm_kernel,
                             cudaFuncAttributeMaxDynamicSharedMemorySize, SMEM_BYTES);
        cfg_done = 1;
    }
    gemm_kernel<<<BATCH / 32, 512, SMEM_BYTES>>>(x, features, fc0_W, fc0_b, a0,
                                                 fc1_W, fc1_b, a1, out);
}

// round 11
// speedup vs baseline: 9.9757x; 1.4907x over previous
#include <cuda_runtime.h>
#include <cstdint>

#define BATCH 4096
#define IN_F 128
#define OUT_F 128
#define NW (IN_F * OUT_F)
#define NCHUNK 37            // 36 x-chunks (9e x 4 i-groups) + 1 bias chunk
#define XP 164               // x smem pitch (floats) = 41 float4

// B operand in EXACT mma-fragment order (tf32-rounded):
// d_Btf[((c*16 + nb)*2 + p)*128 + lane*4 + e2]
//   = Bt[nb*8 + (lane>>2)][c*32 + 16p + 8*(e2>>1) + 4*(e2&1) + (lane&3)]
__device__ float d_Btf[NCHUNK * 16 * 2 * 128];

// ---------------------------------------------------------------------------
// Helpers (baseline PTX only — toolchain compiles via compute_103, no tcgen05)
// ---------------------------------------------------------------------------
__device__ __forceinline__ float tf32r(float x) {
    uint32_t r;
    asm("cvt.rn.tf32.f32 %0, %1;" : "=r"(r) : "f"(x));
    return __uint_as_float(r);
}
__device__ __forceinline__ uint32_t tf32u(float x) {
    uint32_t r;
    asm("cvt.rn.tf32.f32 %0, %1;" : "=r"(r) : "f"(x));
    return r;
}
__device__ __forceinline__ void mma_tf32(float& d0, float& d1, float& d2, float& d3,
                                         uint32_t a0, uint32_t a1, uint32_t a2, uint32_t a3,
                                         uint32_t b0, uint32_t b1) {
    asm volatile(
        "mma.sync.aligned.m16n8k8.row.col.f32.tf32.tf32.f32 "
        "{%0,%1,%2,%3}, {%4,%5,%6,%7}, {%8,%9}, {%0,%1,%2,%3};"
        : "+f"(d0), "+f"(d1), "+f"(d2), "+f"(d3)
        : "r"(a0), "r"(a1), "r"(a2), "r"(a3), "r"(b0), "r"(b1));
}

// ---------------------------------------------------------------------------
// Prep: build d_Btf. Block = (c, nb); thread -> (p, lane, e2). Coalesced write.
//   Bt[o][k]: k<1152: e=k>>7,i=k&127 -> gen_W[(o*128+i)*8+e] (e<8) / gen_b (e==8)
//             1152..1160: bias cols ; else 0
// ---------------------------------------------------------------------------
__global__ __launch_bounds__(256) void b_kernel(const float* __restrict__ gen_W,
                                                const float* __restrict__ gen_b) {
    const int c  = blockIdx.x >> 4;
    const int nb = blockIdx.x & 15;
    const int tid = threadIdx.x;
    const int p  = tid >> 7;
    const int l  = (tid >> 2) & 31;
    const int e2 = tid & 3;
    const int g = l >> 2, q = l & 3;
    const int o = nb * 8 + g;
    const int k = c * 32 + 16 * p + 8 * (e2 >> 1) + 4 * (e2 & 1) + q;
    float v;
    if (k < 1152) {
        const int e = k >> 7, i = k & 127, p8 = o * 128 + i;
        v = (e < 8) ? gen_W[p8 * 8 + e] : gen_b[p8];
    } else if (k < 1161) {
        const int e = k - 1152;
        v = (e < 8) ? gen_W[(NW + o) * 8 + e] : gen_b[NW + o];
    } else v = 0.f;
    d_Btf[blockIdx.x * 256 + tid] = tf32r(v);
}

// ---------------------------------------------------------------------------
// Fused GEMM: out = U @ Bt^T with U[b,k]=c[b,e]*x[b,i] never materialized.
// CTA: 256 thr (8 warps), tile M=64 x N=64; grid 128 = (m-tile 64) x (n-half).
// Warp: wr=wid&3 (16 rows), wc=wid>>2 (32 cols). All-K per warp, NO barriers
// in mainloop. A-frags (tf32(x)) preloaded in 64 regs; per-e scale folded into
// accumulator (z-scheme). B read as fragments via 8 coalesced LDG.128/chunk,
// register double-buffered (depth 1).
// ---------------------------------------------------------------------------
__global__ __launch_bounds__(256, 1) void gemm_kernel(
    const float* __restrict__ x,
    const float* __restrict__ features,
    const float* __restrict__ fc0_W, const float* __restrict__ fc0_b,
    const float* __restrict__ a0p,
    const float* __restrict__ fc1_W, const float* __restrict__ fc1_b,
    const float* __restrict__ a1p,
    float* __restrict__ out)
{
    __shared__ __align__(16) float xs[64 * XP];   // 42 KB: cols 0-127 x, 128-136 c, ..163 zero

    const int tid = threadIdx.x, wid = tid >> 5, lid = tid & 31;
    const int mt = blockIdx.x >> 1, nh = blockIdx.x & 1;
    const int b0row = mt * 64;
    const int wr = wid & 3, wc = wid >> 2;
    const int m0 = wr * 16;
    const int nbb = nh * 8 + wc * 4;              // global n-block base (nb units of 8)
    const int g = lid >> 2, q = lid & 3;

    // ---- x tile: 64 rows x 128 cols (2048 float4, 8/thread, coalesced) ----
    {
        const float4* xg = (const float4*)(x + (size_t)b0row * IN_F);
        float4* xs4 = (float4*)xs;
        #pragma unroll
        for (int j = 0; j < 8; j++) {
            const int idx = tid + 256 * j;
            const int r = idx >> 5, c4 = idx & 31;
            xs4[r * 41 + c4] = xg[idx];
        }
    }

    // ---- tiny MLP: threads 0-63, one sample each; coeffs -> cols 128-136 ----
    if (tid < 64) {
        const int b = b0row + tid;
        const float a0 = a0p[0], a1 = a1p[0];
        float h0[16];
        #pragma unroll
        for (int j = 0; j < 16; j++) {
            float s = fc0_b[j];
            #pragma unroll
            for (int k = 0; k < 10; k++)
                s += features[b * 10 + k] * fc0_W[j * 10 + k];
            h0[j] = (s >= 0.f) ? s : a0 * s;
        }
        float* xr = xs + tid * XP + 128;
        #pragma unroll
        for (int e = 0; e < 8; e++) {
            float s = fc1_b[e];
            #pragma unroll
            for (int j = 0; j < 16; j++)
                s += h0[j] * fc1_W[e * 16 + j];
            xr[e] = (s >= 0.f) ? s : a1 * s;
        }
        xr[8] = 1.f;
        #pragma unroll
        for (int j = 9; j < 36; j++) xr[j] = 0.f;   // zero cols 137..163
    }

    // ---- B fragment pointer + first prefetch (no smem dependency) ----
    const float4* bp = (const float4*)d_Btf;      // f4 index: ((c*16+nb)*2+p)*32 + lane
    float4 br[2][8];                               // [buf][ni*2+p]
    #define LOADB(buf, c)                                                     \
        _Pragma("unroll")                                                     \
        for (int ni = 0; ni < 4; ni++) {                                      \
            _Pragma("unroll")                                                 \
            for (int p = 0; p < 2; p++)                                       \
                br[buf][ni * 2 + p] =                                         \
                    __ldg(bp + (((c) * 16 + nbb + ni) * 2 + p) * 32 + lid);   \
        }
    LOADB(0, 0)

    __syncthreads();

    // ---- A-frag preload: tf32(x), all 4 i-groups (64 regs) ----
    const float* x0 = xs + (m0 + g) * XP;
    const float* x1 = x0 + 8 * XP;
    uint32_t ua0[16], ua1[16], ua2[16], ua3[16];   // [ii*4+ki]
    #pragma unroll
    for (int ii = 0; ii < 4; ii++)
        #pragma unroll
        for (int ki = 0; ki < 4; ki++) {
            const int col = ii * 32 + ki * 8 + q;
            ua0[ii * 4 + ki] = tf32u(x0[col]);
            ua1[ii * 4 + ki] = tf32u(x1[col]);
            ua2[ii * 4 + ki] = tf32u(x0[col + 4]);
            ua3[ii * 4 + ki] = tf32u(x1[col + 4]);
        }

    float acc[16];                                 // [ni*4+r]
    #pragma unroll
    for (int r = 0; r < 16; r++) acc[r] = 0.f;

    // ---- mainloop: e outer (fold), ii inner (chunk), depth-1 B prefetch ----
    for (int e = 0; e < 9; e++) {
        float z[16];
        #pragma unroll
        for (int r = 0; r < 16; r++) z[r] = 0.f;

        #pragma unroll
        for (int ii = 0; ii < 4; ii++) {
            const int c = e * 4 + ii;
            if (c + 1 < NCHUNK) LOADB((ii + 1) & 1, c + 1)

            #pragma unroll
            for (int ki = 0; ki < 4; ki++) {
                const uint32_t a0 = ua0[ii * 4 + ki], a1 = ua1[ii * 4 + ki];
                const uint32_t a2 = ua2[ii * 4 + ki], a3 = ua3[ii * 4 + ki];
                #pragma unroll
                for (int ni = 0; ni < 4; ni++) {
                    const float4 f = br[ii & 1][ni * 2 + (ki >> 1)];
                    const uint32_t bb0 = (ki & 1) ? __float_as_uint(f.z) : __float_as_uint(f.x);
                    const uint32_t bb1 = (ki & 1) ? __float_as_uint(f.w) : __float_as_uint(f.y);
                    mma_tf32(z[ni * 4 + 0], z[ni * 4 + 1], z[ni * 4 + 2], z[ni * 4 + 3],
                             a0, a1, a2, a3, bb0, bb1);
                }
            }
        }

        const float cb0 = x0[128 + e];
        const float cb1 = x1[128 + e];
        #pragma unroll
        for (int ni = 0; ni < 4; ni++) {
            acc[ni * 4 + 0] += cb0 * z[ni * 4 + 0];
            acc[ni * 4 + 1] += cb0 * z[ni * 4 + 1];
            acc[ni * 4 + 2] += cb1 * z[ni * 4 + 2];
            acc[ni * 4 + 3] += cb1 * z[ni * 4 + 3];
        }
    }

    // ---- bias chunk c=36 (coeff cols, scale 1) -> accumulate into acc ----
    {
        #pragma unroll
        for (int ki = 0; ki < 4; ki++) {
            const int col = 128 + ki * 8 + q;
            const uint32_t a0 = tf32u(x0[col]);
            const uint32_t a1 = tf32u(x1[col]);
            const uint32_t a2 = tf32u(x0[col + 4]);
            const uint32_t a3 = tf32u(x1[col + 4]);
            #pragma unroll
            for (int ni = 0; ni < 4; ni++) {
                const float4 f = br[0][ni * 2 + (ki >> 1)];   // 36 & 1 == 0
                const uint32_t bb0 = (ki & 1) ? __float_as_uint(f.z) : __float_as_uint(f.x);
                const uint32_t bb1 = (ki & 1) ? __float_as_uint(f.w) : __float_as_uint(f.y);
                mma_tf32(acc[ni * 4 + 0], acc[ni * 4 + 1], acc[ni * 4 + 2], acc[ni * 4 + 3],
                         a0, a1, a2, a3, bb0, bb1);
            }
        }
    }

    // ---- stores: rows b0row+m0+g / +8, cols nh*64 + wc*32 + ni*8 + 2q ----
    const int colbase = nh * 64 + wc * 32;
    #pragma unroll
    for (int ni = 0; ni < 4; ni++) {
        const int col = colbase + ni * 8 + 2 * q;
        float2 lo = make_float2(acc[ni * 4 + 0], acc[ni * 4 + 1]);
        float2 hi = make_float2(acc[ni * 4 + 2], acc[ni * 4 + 3]);
        *(float2*)(out + (size_t)(b0row + m0 + g)     * OUT_F + col) = lo;
        *(float2*)(out + (size_t)(b0row + m0 + g + 8) * OUT_F + col) = hi;
    }
}

// ---------------------------------------------------------------------------
extern "C" void kernel_launch(void* const* d_in, const int* in_sizes, int n_in,
                              void* d_out, int out_size) {
    const float* x        = (const float*)d_in[0];
    const float* features = (const float*)d_in[1];
    const float* fc0_W    = (const float*)d_in[2];
    const float* fc0_b    = (const float*)d_in[3];
    const float* a0       = (const float*)d_in[4];
    const float* fc1_W    = (const float*)d_in[5];
    const float* fc1_b    = (const float*)d_in[6];
    const float* a1       = (const float*)d_in[7];
    const float* gen_W    = (const float*)d_in[8];
    const float* gen_b    = (const float*)d_in[9];
    float* out = (float*)d_out;

    b_kernel<<<NCHUNK * 16, 256>>>(gen_W, gen_b);
    gemm_kernel<<<128, 256>>>(x, features, fc0_W, fc0_b, a0,
                              fc1_W, fc1_b, a1, out);
}